// round 6
// baseline (speedup 1.0000x reference)
#include <cuda_runtime.h>
#include <cuda_bf16.h>
#include <math.h>

#define SEQ 4096
#define DM  768
#define NH  12
#define HD  64

// Packed fp32x2 ops (sm_103a)
#define PACK2(out, lo, hi) asm("mov.b64 %0, {%1, %2};" : "=l"(out) : "f"(lo), "f"(hi))
#define UNPACK2(lo, hi, in) asm("mov.b64 {%0, %1}, %2;" : "=f"(lo), "=f"(hi) : "l"(in))
#define FMA2(d, a, b) asm("fma.rn.f32x2 %0, %1, %2, %3;" : "=l"(d) : "l"(a), "l"(b), "l"(d))
#define MUL2(d, a, b) asm("mul.rn.f32x2 %0, %1, %2;" : "=l"(d) : "l"(a), "l"(b))

typedef unsigned long long u64;

// Scratch: Q, K, V, CTX each [SEQ, DM] fp32
__device__ float g_q[SEQ * DM];
__device__ float g_k[SEQ * DM];
__device__ float g_v[SEQ * DM];
__device__ float g_ctx[SEQ * DM];

// ---------------------------------------------------------------------------
// 128x128x16 SGEMM, 256 threads, 8x8/thread, f32x2 accumulators,
// double-buffered smem with register prefetch.
// ---------------------------------------------------------------------------
#define AS_STRIDE 20
#define BS_STRIDE 132
#define NKT 48          // DM / 16

__device__ __forceinline__ void gemm128(const float* __restrict__ A,
                                        const float* __restrict__ B,
                                        float* __restrict__ C,
                                        const float* __restrict__ bias) {
    __shared__ float As[2][128 * AS_STRIDE];
    __shared__ float Bs[2][16 * BS_STRIDE];

    const int tid = threadIdx.x;
    const int tx = tid & 15;
    const int ty = tid >> 4;
    const int m0 = blockIdx.y * 128;
    const int n0 = blockIdx.x * 128;

    const int i0 = tid, i1 = tid + 256;
    const int am0 = i0 >> 2, ak0 = (i0 & 3) * 4;
    const int am1 = i1 >> 2, ak1 = (i1 & 3) * 4;
    const int bk0 = i0 >> 5, bn0 = (i0 & 31) * 4;
    const int bk1 = i1 >> 5, bn1 = (i1 & 31) * 4;

    float4 pa0, pa1, pb0, pb1;
    // prefetch tile 0
    pa0 = *(const float4*)(A + (size_t)(m0 + am0) * DM + ak0);
    pa1 = *(const float4*)(A + (size_t)(m0 + am1) * DM + ak1);
    pb0 = *(const float4*)(B + (size_t)bk0 * DM + n0 + bn0);
    pb1 = *(const float4*)(B + (size_t)bk1 * DM + n0 + bn1);
    *(float4*)&As[0][am0 * AS_STRIDE + ak0] = pa0;
    *(float4*)&As[0][am1 * AS_STRIDE + ak1] = pa1;
    *(float4*)&Bs[0][bk0 * BS_STRIDE + bn0] = pb0;
    *(float4*)&Bs[0][bk1 * BS_STRIDE + bn1] = pb1;
    __syncthreads();

    u64 acc[8][4];
#pragma unroll
    for (int i = 0; i < 8; i++)
#pragma unroll
        for (int j = 0; j < 4; j++) acc[i][j] = 0ULL;

    for (int t = 0; t < NKT; t++) {
        const int cur = t & 1;
        if (t + 1 < NKT) {
            const int k0 = (t + 1) * 16;
            pa0 = *(const float4*)(A + (size_t)(m0 + am0) * DM + k0 + ak0);
            pa1 = *(const float4*)(A + (size_t)(m0 + am1) * DM + k0 + ak1);
            pb0 = *(const float4*)(B + (size_t)(k0 + bk0) * DM + n0 + bn0);
            pb1 = *(const float4*)(B + (size_t)(k0 + bk1) * DM + n0 + bn1);
        }

        const float* Ac = As[cur];
        const float* Bc = Bs[cur];
#pragma unroll
        for (int k4 = 0; k4 < 4; k4++) {
            float4 a4[8];
#pragma unroll
            for (int i = 0; i < 8; i++)
                a4[i] = *(const float4*)&Ac[(ty * 8 + i) * AS_STRIDE + k4 * 4];
#pragma unroll
            for (int kk = 0; kk < 4; kk++) {
                const float* bp = &Bc[(k4 * 4 + kk) * BS_STRIDE + tx * 8];
                const ulonglong2 b01 = *(const ulonglong2*)bp;
                const ulonglong2 b23 = *(const ulonglong2*)(bp + 4);
#pragma unroll
                for (int i = 0; i < 8; i++) {
                    const float av = (kk == 0) ? a4[i].x : (kk == 1) ? a4[i].y
                                   : (kk == 2) ? a4[i].z : a4[i].w;
                    u64 a2; PACK2(a2, av, av);
                    FMA2(acc[i][0], a2, b01.x);
                    FMA2(acc[i][1], a2, b01.y);
                    FMA2(acc[i][2], a2, b23.x);
                    FMA2(acc[i][3], a2, b23.y);
                }
            }
        }
        __syncthreads();
        if (t + 1 < NKT) {
            const int nxt = cur ^ 1;
            *(float4*)&As[nxt][am0 * AS_STRIDE + ak0] = pa0;
            *(float4*)&As[nxt][am1 * AS_STRIDE + ak1] = pa1;
            *(float4*)&Bs[nxt][bk0 * BS_STRIDE + bn0] = pb0;
            *(float4*)&Bs[nxt][bk1 * BS_STRIDE + bn1] = pb1;
            __syncthreads();
        }
    }

#pragma unroll
    for (int i = 0; i < 8; i++) {
        const int m = m0 + ty * 8 + i;
        const int n = n0 + tx * 8;
        float o[8];
#pragma unroll
        for (int j = 0; j < 4; j++) UNPACK2(o[2 * j], o[2 * j + 1], acc[i][j]);
        if (bias) {
#pragma unroll
            for (int j = 0; j < 8; j++) o[j] += bias[n + j];
        }
        *(float4*)(C + (size_t)m * DM + n)     = make_float4(o[0], o[1], o[2], o[3]);
        *(float4*)(C + (size_t)m * DM + n + 4) = make_float4(o[4], o[5], o[6], o[7]);
    }
}

__global__ __launch_bounds__(256) void qkv_kernel(const float* __restrict__ x,
                                                  const float* __restrict__ wq,
                                                  const float* __restrict__ wk,
                                                  const float* __restrict__ wv) {
    const float* W;
    float* O;
    if (blockIdx.z == 0)      { W = wq; O = g_q; }
    else if (blockIdx.z == 1) { W = wk; O = g_k; }
    else                      { W = wv; O = g_v; }
    gemm128(x, W, O, nullptr);
}

__global__ __launch_bounds__(256) void out_proj_kernel(const float* __restrict__ wo,
                                                       const float* __restrict__ bo,
                                                       float* __restrict__ out) {
    gemm128(g_ctx, wo, out, bo);
}

// ---------------------------------------------------------------------------
// Flash attention (causal), fp32, packed f32x2.
// CTA = 128 queries x one head; 128-key tiles. 256 threads (16x16).
// S computed in two 4-row halves to cap register pressure.
// ---------------------------------------------------------------------------
#define BQ 128
#define BK 128
#define QS_STR 68
#define KT_STR 132
#define VS_STR 68
#define PS_STR 132
#define FLASH_SMEM ((BQ * QS_STR + HD * KT_STR + BK * VS_STR + BQ * PS_STR) * 4)

__global__ __launch_bounds__(256, 1) void flash_kernel() {
    extern __shared__ float sm[];
    float* Qs = sm;
    float* Kt = Qs + BQ * QS_STR;
    float* Vs = Kt + HD * KT_STR;
    float* Ps = Vs + BK * VS_STR;

    const int tid = threadIdx.x;
    const int tx = tid & 15;
    const int ty = tid >> 4;
    const int qb = (gridDim.x - 1) - blockIdx.x;   // heavy CTAs first
    const int h = blockIdx.y;
    const int q0 = qb * BQ;

    // Load Q tile natural [r][d]
#pragma unroll
    for (int t = 0; t < 8; t++) {
        const int idx = tid + t * 256;
        const int r = idx >> 4;
        const int d4 = (idx & 15) * 4;
        *(float4*)&Qs[r * QS_STR + d4] =
            *(const float4*)(g_q + (size_t)(q0 + r) * DM + h * HD + d4);
    }

    float m_i[8], l_i[8];
    u64 O2[8][2];
#pragma unroll
    for (int i = 0; i < 8; i++) {
        m_i[i] = -1e30f; l_i[i] = 0.f; O2[i][0] = 0ULL; O2[i][1] = 0ULL;
    }

    for (int kb = 0; kb <= qb; kb++) {
        const int k0g = kb * BK;
        __syncthreads();   // prev iter done with Kt/Vs/Ps (covers Q load on iter 0)

        // K: row-per-lane mapping -> conflict-free transpose stores.
        // V: coalesced mapping, natural layout.
#pragma unroll
        for (int t = 0; t < 8; t++) {
            const int idx = tid + t * 256;
            const int rk = idx & 127;
            const int dk = (idx >> 7) * 4;
            const float4 kv = *(const float4*)(g_k + (size_t)(k0g + rk) * DM + h * HD + dk);
            Kt[(dk + 0) * KT_STR + rk] = kv.x;
            Kt[(dk + 1) * KT_STR + rk] = kv.y;
            Kt[(dk + 2) * KT_STR + rk] = kv.z;
            Kt[(dk + 3) * KT_STR + rk] = kv.w;
            const int rv = idx >> 4;
            const int dv = (idx & 15) * 4;
            *(float4*)&Vs[rv * VS_STR + dv] =
                *(const float4*)(g_v + (size_t)(k0g + rv) * DM + h * HD + dv);
        }
        __syncthreads();

        const bool diag = (kb == qb);

        // S = Q K^T + online softmax, 4 rows at a time (register cap)
#pragma unroll
        for (int half = 0; half < 2; half++) {
            u64 s2[4][4];
#pragma unroll
            for (int i = 0; i < 4; i++)
#pragma unroll
                for (int j = 0; j < 4; j++) s2[i][j] = 0ULL;

#pragma unroll 8
            for (int d = 0; d < HD; d++) {
                const float* kp = &Kt[d * KT_STR + tx * 8];
                const ulonglong2 k01 = *(const ulonglong2*)kp;
                const ulonglong2 k23 = *(const ulonglong2*)(kp + 4);
#pragma unroll
                for (int i = 0; i < 4; i++) {
                    const float qv = Qs[(ty * 8 + half * 4 + i) * QS_STR + d];
                    u64 q2; PACK2(q2, qv, qv);
                    FMA2(s2[i][0], q2, k01.x);
                    FMA2(s2[i][1], q2, k01.y);
                    FMA2(s2[i][2], q2, k23.x);
                    FMA2(s2[i][3], q2, k23.y);
                }
            }

#pragma unroll
            for (int i = 0; i < 4; i++) {
                const int ri = half * 4 + i;
                float s[8];
#pragma unroll
                for (int j = 0; j < 4; j++) UNPACK2(s[2 * j], s[2 * j + 1], s2[i][j]);
                const int rg = q0 + ty * 8 + ri;
#pragma unroll
                for (int j = 0; j < 8; j++) {
                    s[j] *= 0.125f;   // 1/sqrt(64)
                    if (diag && (k0g + tx * 8 + j) > rg) s[j] = -1e30f;
                }
                float mx = s[0];
#pragma unroll
                for (int j = 1; j < 8; j++) mx = fmaxf(mx, s[j]);
#pragma unroll
                for (int off = 8; off; off >>= 1)
                    mx = fmaxf(mx, __shfl_xor_sync(0xffffffffu, mx, off));
                const float mnew = fmaxf(m_i[ri], mx);
                float rs = 0.f;
#pragma unroll
                for (int j = 0; j < 8; j++) { s[j] = __expf(s[j] - mnew); rs += s[j]; }
#pragma unroll
                for (int off = 8; off; off >>= 1)
                    rs += __shfl_xor_sync(0xffffffffu, rs, off);
                const float alpha = __expf(m_i[ri] - mnew);
                m_i[ri] = mnew;
                l_i[ri] = l_i[ri] * alpha + rs;
                u64 a2; PACK2(a2, alpha, alpha);
                MUL2(O2[ri][0], O2[ri][0], a2);
                MUL2(O2[ri][1], O2[ri][1], a2);
                *(float4*)&Ps[(ty * 8 + ri) * PS_STR + tx * 8] =
                    make_float4(s[0], s[1], s[2], s[3]);
                *(float4*)&Ps[(ty * 8 + ri) * PS_STR + tx * 8 + 4] =
                    make_float4(s[4], s[5], s[6], s[7]);
            }
        }
        __syncthreads();   // P fully written

        // O += P V : p vectorized over 4 columns, V as LDS.128 -> 2 u64
#pragma unroll 2
        for (int c4 = 0; c4 < BK / 4; c4++) {
            float4 p4[8];
#pragma unroll
            for (int i = 0; i < 8; i++)
                p4[i] = *(const float4*)&Ps[(ty * 8 + i) * PS_STR + c4 * 4];
#pragma unroll
            for (int cc = 0; cc < 4; cc++) {
                const ulonglong2 v2 = *(const ulonglong2*)&Vs[(c4 * 4 + cc) * VS_STR + tx * 4];
#pragma unroll
                for (int i = 0; i < 8; i++) {
                    const float pv = (cc == 0) ? p4[i].x : (cc == 1) ? p4[i].y
                                   : (cc == 2) ? p4[i].z : p4[i].w;
                    u64 p2; PACK2(p2, pv, pv);
                    FMA2(O2[i][0], p2, v2.x);
                    FMA2(O2[i][1], p2, v2.y);
                }
            }
        }
    }

    // Epilogue
#pragma unroll
    for (int i = 0; i < 8; i++) {
        const float inv = 1.0f / l_i[i];
        float o[4];
        UNPACK2(o[0], o[1], O2[i][0]);
        UNPACK2(o[2], o[3], O2[i][1]);
        const int row = q0 + ty * 8 + i;
        *(float4*)(g_ctx + (size_t)row * DM + h * HD + tx * 4) =
            make_float4(o[0] * inv, o[1] * inv, o[2] * inv, o[3] * inv);
    }
}

// ---------------------------------------------------------------------------
extern "C" void kernel_launch(void* const* d_in, const int* in_sizes, int n_in,
                              void* d_out, int out_size) {
    const float* x  = (const float*)d_in[0];
    const float* wq = (const float*)d_in[1];
    const float* wk = (const float*)d_in[2];
    const float* wv = (const float*)d_in[3];
    const float* wo = (const float*)d_in[4];
    const float* bo = (const float*)d_in[5];
    float* out = (float*)d_out;

    cudaFuncSetAttribute(flash_kernel, cudaFuncAttributeMaxDynamicSharedMemorySize,
                         FLASH_SMEM);

    qkv_kernel<<<dim3(DM / 128, SEQ / 128, 3), 256>>>(x, wq, wk, wv);
    flash_kernel<<<dim3(SEQ / BQ, NH), 256, FLASH_SMEM>>>();
    out_proj_kernel<<<dim3(DM / 128, SEQ / 128), 256>>>(wo, bo, out);
}

// round 7
// speedup vs baseline: 3.5664x; 3.5664x over previous
#include <cuda_runtime.h>
#include <cuda_bf16.h>
#include <math.h>

#define SEQ 4096
#define DM  768
#define NH  12
#define HD  64

typedef unsigned int u32;

// tf32 round-to-nearest from fp32 (result is fp32 bit-pattern w/ low mantissa 0)
__device__ __forceinline__ u32 f2tf(float f) {
    u32 u; asm("cvt.rna.tf32.f32 %0, %1;" : "=r"(u) : "f"(f)); return u;
}
__device__ __forceinline__ float f2tff(float f) { return __uint_as_float(f2tf(f)); }

// D(16x8) += A(16x8) * B(8x8), tf32 inputs, fp32 accum
#define MMA_TF32(d, a0, a1, a2, a3, b0, b1)                                        \
    asm volatile(                                                                  \
        "mma.sync.aligned.m16n8k8.row.col.f32.tf32.tf32.f32 "                      \
        "{%0,%1,%2,%3},{%4,%5,%6,%7},{%8,%9},{%0,%1,%2,%3};"                       \
        : "+f"((d)[0]), "+f"((d)[1]), "+f"((d)[2]), "+f"((d)[3])                   \
        : "r"(a0), "r"(a1), "r"(a2), "r"(a3), "r"(b0), "r"(b1))

// Scratch: Q, K, V, CTX each [SEQ, DM] fp32
__device__ float g_q[SEQ * DM];
__device__ float g_k[SEQ * DM];
__device__ float g_v[SEQ * DM];
__device__ float g_ctx[SEQ * DM];

// ---------------------------------------------------------------------------
// 128x128x32 GEMM via mma.sync tf32. 8 warps, warp = 32m x 64n.
// ---------------------------------------------------------------------------
#define AS_STR 36
#define BS_STR 136

__device__ __forceinline__ void gemm_mma(const float* __restrict__ A,
                                         const float* __restrict__ B,
                                         float* __restrict__ C,
                                         const float* __restrict__ bias) {
    __shared__ float As[128 * AS_STR];   // [m][k] 128x32
    __shared__ float Bs[32 * BS_STR];    // [k][n] 32x128

    const int tid = threadIdx.x;
    const int lane = tid & 31;
    const int wid = tid >> 5;
    const int gid = lane >> 2;      // 0..7
    const int tig = lane & 3;       // 0..3
    const int wm = wid >> 1;        // 0..3  -> 32 rows each
    const int wn = wid & 1;         // 0..1  -> 64 cols each
    const int m0 = blockIdx.y * 128;
    const int n0 = blockIdx.x * 128;

    float c[2][8][4];
#pragma unroll
    for (int i = 0; i < 2; i++)
#pragma unroll
        for (int f = 0; f < 8; f++)
#pragma unroll
            for (int j = 0; j < 4; j++) c[i][f][j] = 0.f;

    for (int k0 = 0; k0 < DM; k0 += 32) {
        // Load + tf32-convert A (128x32) and B (32x128)
#pragma unroll
        for (int t = 0; t < 4; t++) {
            const int idx = tid + t * 256;
            const int m = idx >> 3;
            const int kq = (idx & 7) * 4;
            float4 a = *(const float4*)(A + (size_t)(m0 + m) * DM + k0 + kq);
            a.x = f2tff(a.x); a.y = f2tff(a.y); a.z = f2tff(a.z); a.w = f2tff(a.w);
            *(float4*)&As[m * AS_STR + kq] = a;

            const int kb = idx >> 5;
            const int nb = (idx & 31) * 4;
            float4 b = *(const float4*)(B + (size_t)(k0 + kb) * DM + n0 + nb);
            b.x = f2tff(b.x); b.y = f2tff(b.y); b.z = f2tff(b.z); b.w = f2tff(b.w);
            *(float4*)&Bs[kb * BS_STR + nb] = b;
        }
        __syncthreads();

#pragma unroll
        for (int k8 = 0; k8 < 4; k8++) {
            u32 a0[2], a1[2], a2[2], a3[2];
#pragma unroll
            for (int fm = 0; fm < 2; fm++) {
                const int rb = wm * 32 + fm * 16;
                const int kc = k8 * 8 + tig;
                a0[fm] = __float_as_uint(As[(rb + gid)     * AS_STR + kc]);
                a1[fm] = __float_as_uint(As[(rb + gid + 8) * AS_STR + kc]);
                a2[fm] = __float_as_uint(As[(rb + gid)     * AS_STR + kc + 4]);
                a3[fm] = __float_as_uint(As[(rb + gid + 8) * AS_STR + kc + 4]);
            }
#pragma unroll
            for (int f = 0; f < 8; f++) {
                const int nc = wn * 64 + f * 8 + gid;
                const u32 b0 = __float_as_uint(Bs[(k8 * 8 + tig)     * BS_STR + nc]);
                const u32 b1 = __float_as_uint(Bs[(k8 * 8 + tig + 4) * BS_STR + nc]);
                MMA_TF32(c[0][f], a0[0], a1[0], a2[0], a3[0], b0, b1);
                MMA_TF32(c[1][f], a0[1], a1[1], a2[1], a3[1], b0, b1);
            }
        }
        __syncthreads();
    }

    // Epilogue
#pragma unroll
    for (int fm = 0; fm < 2; fm++) {
        const int r1 = m0 + wm * 32 + fm * 16 + gid;
#pragma unroll
        for (int f = 0; f < 8; f++) {
            const int n = n0 + wn * 64 + f * 8 + 2 * tig;
            float b0 = 0.f, b1 = 0.f;
            if (bias) { b0 = bias[n]; b1 = bias[n + 1]; }
            *(float2*)(C + (size_t)r1 * DM + n) =
                make_float2(c[fm][f][0] + b0, c[fm][f][1] + b1);
            *(float2*)(C + (size_t)(r1 + 8) * DM + n) =
                make_float2(c[fm][f][2] + b0, c[fm][f][3] + b1);
        }
    }
}

__global__ __launch_bounds__(256, 2) void qkv_kernel(const float* __restrict__ x,
                                                     const float* __restrict__ wq,
                                                     const float* __restrict__ wk,
                                                     const float* __restrict__ wv) {
    const float* W;
    float* O;
    if (blockIdx.z == 0)      { W = wq; O = g_q; }
    else if (blockIdx.z == 1) { W = wk; O = g_k; }
    else                      { W = wv; O = g_v; }
    gemm_mma(x, W, O, nullptr);
}

__global__ __launch_bounds__(256, 2) void out_proj_kernel(const float* __restrict__ wo,
                                                          const float* __restrict__ bo,
                                                          float* __restrict__ out) {
    gemm_mma(g_ctx, wo, out, bo);
}

// ---------------------------------------------------------------------------
// Flash attention (causal) via mma.sync tf32.
// CTA = 128 queries x 1 head, 128-key tiles, 8 warps; warp = 16 rows.
// ---------------------------------------------------------------------------
#define QS_STR 68
#define KS_STR 68
#define VS_STR 72
#define PS_STR 132
#define FLASH_SMEM ((128 * QS_STR + 128 * KS_STR + 128 * VS_STR + 128 * PS_STR) * 4)

__global__ __launch_bounds__(256, 1) void flash_kernel() {
    extern __shared__ float smf[];
    float* Qs = smf;                       // [q][d] 128x64
    float* Ks = Qs + 128 * QS_STR;         // [k][d] 128x64
    float* Vs = Ks + 128 * KS_STR;         // [k][d] 128x64
    float* Ps = Vs + 128 * VS_STR;         // [q][k] 128x128

    const int tid = threadIdx.x;
    const int lane = tid & 31;
    const int wid = tid >> 5;
    const int gid = lane >> 2;
    const int tig = lane & 3;
    const int rw = wid * 16;
    const int qb = (gridDim.x - 1) - blockIdx.x;   // heavy CTAs first
    const int h = blockIdx.y;
    const int q0 = qb * 128;

    // Load Q (scaled by 1/sqrt(HD), tf32-rounded)
#pragma unroll
    for (int t = 0; t < 8; t++) {
        const int idx = tid + t * 256;
        const int r = idx >> 4;
        const int d4 = (idx & 15) * 4;
        float4 q = *(const float4*)(g_q + (size_t)(q0 + r) * DM + h * HD + d4);
        q.x = f2tff(q.x * 0.125f); q.y = f2tff(q.y * 0.125f);
        q.z = f2tff(q.z * 0.125f); q.w = f2tff(q.w * 0.125f);
        *(float4*)&Qs[r * QS_STR + d4] = q;
    }

    const int row1 = q0 + rw + gid;
    const int row2 = row1 + 8;
    float m1 = -1e30f, m2 = -1e30f, l1 = 0.f, l2 = 0.f;
    float o[8][4];
#pragma unroll
    for (int f = 0; f < 8; f++)
#pragma unroll
        for (int j = 0; j < 4; j++) o[f][j] = 0.f;

    for (int kb = 0; kb <= qb; kb++) {
        const int k0g = kb * 128;
        __syncthreads();   // prev PV done (iter0: Q stores done)

        // Load K, V (tf32-rounded)
#pragma unroll
        for (int t = 0; t < 8; t++) {
            const int idx = tid + t * 256;
            const int r = idx >> 4;
            const int d4 = (idx & 15) * 4;
            float4 k = *(const float4*)(g_k + (size_t)(k0g + r) * DM + h * HD + d4);
            k.x = f2tff(k.x); k.y = f2tff(k.y); k.z = f2tff(k.z); k.w = f2tff(k.w);
            *(float4*)&Ks[r * KS_STR + d4] = k;
            float4 v = *(const float4*)(g_v + (size_t)(k0g + r) * DM + h * HD + d4);
            v.x = f2tff(v.x); v.y = f2tff(v.y); v.z = f2tff(v.z); v.w = f2tff(v.w);
            *(float4*)&Vs[r * VS_STR + d4] = v;
        }
        __syncthreads();

        // S = Q K^T : 16 n8-frags across 128 keys
        float s[16][4];
#pragma unroll
        for (int f = 0; f < 16; f++)
#pragma unroll
            for (int j = 0; j < 4; j++) s[f][j] = 0.f;

#pragma unroll
        for (int d8 = 0; d8 < 8; d8++) {
            const int dc = d8 * 8 + tig;
            const u32 a0 = __float_as_uint(Qs[(rw + gid)     * QS_STR + dc]);
            const u32 a1 = __float_as_uint(Qs[(rw + gid + 8) * QS_STR + dc]);
            const u32 a2 = __float_as_uint(Qs[(rw + gid)     * QS_STR + dc + 4]);
            const u32 a3 = __float_as_uint(Qs[(rw + gid + 8) * QS_STR + dc + 4]);
#pragma unroll
            for (int f = 0; f < 16; f++) {
                const u32 b0 = __float_as_uint(Ks[(f * 8 + gid) * KS_STR + dc]);
                const u32 b1 = __float_as_uint(Ks[(f * 8 + gid) * KS_STR + dc + 4]);
                MMA_TF32(s[f], a0, a1, a2, a3, b0, b1);
            }
        }

        // Causal mask (diag tile only)
        if (kb == qb) {
#pragma unroll
            for (int f = 0; f < 16; f++) {
                const int cb = k0g + f * 8 + 2 * tig;
                if (cb     > row1) s[f][0] = -1e30f;
                if (cb + 1 > row1) s[f][1] = -1e30f;
                if (cb     > row2) s[f][2] = -1e30f;
                if (cb + 1 > row2) s[f][3] = -1e30f;
            }
        }

        // Online softmax (quad reductions)
        float mx1 = -1e30f, mx2 = -1e30f;
#pragma unroll
        for (int f = 0; f < 16; f++) {
            mx1 = fmaxf(mx1, fmaxf(s[f][0], s[f][1]));
            mx2 = fmaxf(mx2, fmaxf(s[f][2], s[f][3]));
        }
#pragma unroll
        for (int off = 1; off <= 2; off <<= 1) {
            mx1 = fmaxf(mx1, __shfl_xor_sync(0xffffffffu, mx1, off));
            mx2 = fmaxf(mx2, __shfl_xor_sync(0xffffffffu, mx2, off));
        }
        const float mn1 = fmaxf(m1, mx1);
        const float mn2 = fmaxf(m2, mx2);
        float rs1 = 0.f, rs2 = 0.f;
#pragma unroll
        for (int f = 0; f < 16; f++) {
            s[f][0] = __expf(s[f][0] - mn1);
            s[f][1] = __expf(s[f][1] - mn1);
            s[f][2] = __expf(s[f][2] - mn2);
            s[f][3] = __expf(s[f][3] - mn2);
            rs1 += s[f][0] + s[f][1];
            rs2 += s[f][2] + s[f][3];
        }
#pragma unroll
        for (int off = 1; off <= 2; off <<= 1) {
            rs1 += __shfl_xor_sync(0xffffffffu, rs1, off);
            rs2 += __shfl_xor_sync(0xffffffffu, rs2, off);
        }
        const float al1 = __expf(m1 - mn1);
        const float al2 = __expf(m2 - mn2);
        m1 = mn1; m2 = mn2;
        l1 = l1 * al1 + rs1;
        l2 = l2 * al2 + rs2;
#pragma unroll
        for (int f = 0; f < 8; f++) {
            o[f][0] *= al1; o[f][1] *= al1;
            o[f][2] *= al2; o[f][3] *= al2;
        }
        // Store P (tf32-rounded)
#pragma unroll
        for (int f = 0; f < 16; f++) {
            const int cc = f * 8 + 2 * tig;
            *(float2*)&Ps[(rw + gid) * PS_STR + cc] =
                make_float2(f2tff(s[f][0]), f2tff(s[f][1]));
            *(float2*)&Ps[(rw + gid + 8) * PS_STR + cc] =
                make_float2(f2tff(s[f][2]), f2tff(s[f][3]));
        }
        __syncthreads();   // P visible

        // O += P V
#pragma unroll
        for (int k8 = 0; k8 < 16; k8++) {
            const int kc = k8 * 8 + tig;
            const u32 a0 = __float_as_uint(Ps[(rw + gid)     * PS_STR + kc]);
            const u32 a1 = __float_as_uint(Ps[(rw + gid + 8) * PS_STR + kc]);
            const u32 a2 = __float_as_uint(Ps[(rw + gid)     * PS_STR + kc + 4]);
            const u32 a3 = __float_as_uint(Ps[(rw + gid + 8) * PS_STR + kc + 4]);
#pragma unroll
            for (int f = 0; f < 8; f++) {
                const u32 b0 = __float_as_uint(Vs[(k8 * 8 + tig)     * VS_STR + f * 8 + gid]);
                const u32 b1 = __float_as_uint(Vs[(k8 * 8 + tig + 4) * VS_STR + f * 8 + gid]);
                MMA_TF32(o[f], a0, a1, a2, a3, b0, b1);
            }
        }
    }

    // Epilogue
    const float inv1 = 1.0f / l1;
    const float inv2 = 1.0f / l2;
#pragma unroll
    for (int f = 0; f < 8; f++) {
        const int d = h * HD + f * 8 + 2 * tig;
        *(float2*)(g_ctx + (size_t)(q0 + rw + gid) * DM + d) =
            make_float2(o[f][0] * inv1, o[f][1] * inv1);
        *(float2*)(g_ctx + (size_t)(q0 + rw + gid + 8) * DM + d) =
            make_float2(o[f][2] * inv2, o[f][3] * inv2);
    }
}

// ---------------------------------------------------------------------------
extern "C" void kernel_launch(void* const* d_in, const int* in_sizes, int n_in,
                              void* d_out, int out_size) {
    const float* x  = (const float*)d_in[0];
    const float* wq = (const float*)d_in[1];
    const float* wk = (const float*)d_in[2];
    const float* wv = (const float*)d_in[3];
    const float* wo = (const float*)d_in[4];
    const float* bo = (const float*)d_in[5];
    float* out = (float*)d_out;

    cudaFuncSetAttribute(flash_kernel, cudaFuncAttributeMaxDynamicSharedMemorySize,
                         FLASH_SMEM);

    qkv_kernel<<<dim3(DM / 128, SEQ / 128, 3), 256>>>(x, wq, wk, wv);
    flash_kernel<<<dim3(SEQ / 128, NH), 256, FLASH_SMEM>>>();
    out_proj_kernel<<<dim3(DM / 128, SEQ / 128), 256>>>(wo, bo, out);
}